// round 9
// baseline (speedup 1.0000x reference)
#include <cuda_runtime.h>
#include <cstdint>
#include <cmath>
#include <complex>

// ---------------------------------------------------------------------------
// Problem constants
// ---------------------------------------------------------------------------
#define MAX_NODES 50000
#define NF_STRIDE 36   // 1 (s) + 9 (p) + 25 (d) + pad
#define H_STRIDE 68    // 64 + pad(4): conflict-free LDS.128/STS.128 layout

__device__ float g_nodefeat[MAX_NODES * NF_STRIDE];

// Weights live in the constant bank: separate datapath from L1TEX, built for
// warp-uniform broadcast. One shared buffer, re-filled before each kernel.
__constant__ float c_w1[640];          // 10 x 64
__constant__ float c_w2[64 * 160];     // up to 64 x 160 (d); s/p use a prefix

// All real Wigner-3j tables, passed by value (constant bank, param space)
struct W3JParams {
    float w000[1];
    float w011[9];
    float w022[25];
    float w101[9];
    float w110[9];
    float w112[45];
    float w121[45];
    float w202[25];
    float w211[45];
    float w220[25];
    float w222[125];
};

// ---------------------------------------------------------------------------
// Host-side Wigner-3j computation (pure, cheap)
// ---------------------------------------------------------------------------
typedef std::complex<double> cd;

static double factd(int n) { double r = 1.0; for (int i = 2; i <= n; i++) r *= i; return r; }

static double cgc(int j1, int m1, int j2, int m2, int j3, int m3) {
    if (m1 + m2 != m3) return 0.0;
    double pre = std::sqrt((2.0 * j3 + 1.0) * factd(j1 + j2 - j3) * factd(j1 - j2 + j3) *
                           factd(-j1 + j2 + j3) / factd(j1 + j2 + j3 + 1));
    pre *= std::sqrt(factd(j1 + m1) * factd(j1 - m1) * factd(j2 + m2) * factd(j2 - m2) *
                     factd(j3 + m3) * factd(j3 - m3));
    int kmin = 0;
    if (j2 - j3 - m1 > kmin) kmin = j2 - j3 - m1;
    if (j1 - j3 + m2 > kmin) kmin = j1 - j3 + m2;
    int kmax = j1 + j2 - j3;
    if (j1 - m1 < kmax) kmax = j1 - m1;
    if (j2 + m2 < kmax) kmax = j2 + m2;
    double s = 0.0;
    for (int k = kmin; k <= kmax; k++) {
        double term = 1.0 / (factd(k) * factd(j1 + j2 - j3 - k) * factd(j1 - m1 - k) *
                             factd(j2 + m2 - k) * factd(j3 - j2 + m1 + k) * factd(j3 - j1 - m2 + k));
        s += (k & 1) ? -term : term;
    }
    return pre * s;
}

static void qmat(int l, cd* Q) {
    int n = 2 * l + 1;
    for (int i = 0; i < n * n; i++) Q[i] = cd(0, 0);
    Q[l * n + l] = cd(1, 0);
    double is2 = 1.0 / std::sqrt(2.0);
    for (int m = 1; m <= l; m++) {
        double sg = (m & 1) ? -1.0 : 1.0;
        Q[(l + m) * n + (l + m)] = cd(sg * is2, 0);
        Q[(l + m) * n + (l - m)] = cd(is2, 0);
        Q[(l - m) * n + (l - m)] = cd(0, is2);
        Q[(l - m) * n + (l + m)] = cd(0, -sg * is2);
    }
}

static void w3jfill(int l1, int l2, int l3, float* outv) {
    int n1 = 2 * l1 + 1, n2 = 2 * l2 + 1, n3 = 2 * l3 + 1;
    cd Q1[25], Q2[25], Q3[25];
    qmat(l1, Q1); qmat(l2, Q2); qmat(l3, Q3);
    cd R[125];
    for (int a = 0; a < n1; a++)
        for (int c = 0; c < n2; c++)
            for (int e = 0; e < n3; e++) {
                cd acc(0, 0);
                for (int b = 0; b < n1; b++)
                    for (int d = 0; d < n2; d++)
                        for (int f = 0; f < n3; f++) {
                            double Cv = cgc(l1, b - l1, l2, d - l2, l3, f - l3);
                            if (Cv == 0.0) continue;
                            acc += std::conj(Q1[a * n1 + b]) * std::conj(Q2[c * n2 + d]) *
                                   Q3[e * n3 + f] * Cv;
                        }
                R[(a * n2 + c) * n3 + e] = acc;
            }
    int N = n1 * n2 * n3;
    double mr = 0, mi = 0;
    for (int i = 0; i < N; i++) {
        double re = std::fabs(R[i].real()), im = std::fabs(R[i].imag());
        if (re > mr) mr = re;
        if (im > mi) mi = im;
    }
    double tmp[125];
    if (mi > mr)
        for (int i = 0; i < N; i++) tmp[i] = R[i].imag();
    else
        for (int i = 0; i < N; i++) tmp[i] = R[i].real();
    double nrm = 0;
    for (int i = 0; i < N; i++) nrm += tmp[i] * tmp[i];
    nrm = std::sqrt(nrm);
    for (int i = 0; i < N; i++) outv[i] = (float)(tmp[i] / nrm);
}

static void build_w3j(W3JParams* W) {
    w3jfill(0, 0, 0, W->w000);
    w3jfill(0, 1, 1, W->w011);
    w3jfill(0, 2, 2, W->w022);
    w3jfill(1, 0, 1, W->w101);
    w3jfill(1, 1, 0, W->w110);
    w3jfill(1, 1, 2, W->w112);
    w3jfill(1, 2, 1, W->w121);
    w3jfill(2, 0, 2, W->w202);
    w3jfill(2, 1, 1, W->w211);
    w3jfill(2, 2, 0, W->w220);
    w3jfill(2, 2, 2, W->w222);
}

// ---------------------------------------------------------------------------
// f32x2 packed-FMA helpers (sm_103a; PTX-only instruction)
// ---------------------------------------------------------------------------
__device__ __forceinline__ uint64_t pack2(float lo, float hi) {
    uint64_t r;
    asm("mov.b64 %0, {%1, %2};" : "=l"(r) : "f"(lo), "f"(hi));
    return r;
}
__device__ __forceinline__ void fma2(uint64_t& d, uint64_t a, uint64_t b) {
    asm("fma.rn.f32x2 %0, %1, %2, %0;" : "+l"(d) : "l"(a), "l"(b));
}
__device__ __forceinline__ float2 unpack2(uint64_t v) {
    float2 f;
    asm("mov.b64 {%0, %1}, %2;" : "=f"(f.x), "=f"(f.y) : "l"(v));
    return f;
}

// Vector reduction: 4 contiguous f32 atomic adds in one L1TEX wavefront.
__device__ __forceinline__ void red_add_v4(float* p, float a, float b, float c, float d) {
    asm volatile("red.global.add.v4.f32 [%0], {%1, %2, %3, %4};"
                 :: "l"(p), "f"(a), "f"(b), "f"(c), "f"(d)
                 : "memory");
}

// ---------------------------------------------------------------------------
// Device helpers
// ---------------------------------------------------------------------------
__device__ __forceinline__ float scalar_as_float(const int* p) {
    int iv = *p;
    return (iv > -100000000 && iv < 100000000) ? (float)iv : __int_as_float(iv);
}

__device__ __forceinline__ void edge_common(int row, int col, const float* __restrict__ pos,
                                            float maxr, float sh1[3], float sh2[5],
                                            float emb[10]) {
    float vx = pos[3 * row + 0] - pos[3 * col + 0];
    float vy = pos[3 * row + 1] - pos[3 * col + 1];
    float vz = pos[3 * row + 2] - pos[3 * col + 2];
    float d = sqrtf(vx * vx + vy * vy + vz * vz + 1e-12f);
    float inv = 1.0f / d;
    float x = vx * inv, y = vy * inv, z = vz * inv;
    sh1[0] = 1.7320508075688772f * y;
    sh1[1] = 1.7320508075688772f * z;
    sh1[2] = 1.7320508075688772f * x;
    sh2[0] = 3.872983346207417f * x * y;
    sh2[1] = 3.872983346207417f * y * z;
    sh2[2] = 1.118033988749895f * (3.0f * z * z - 1.0f);
    sh2[3] = 3.872983346207417f * x * z;
    sh2[4] = 1.9364916731037085f * (x * x - y * y);

    float invstep = 11.0f / maxr;
    const float EC = 26.6692982f;  // 1.14136 * e^2 * sqrt(10)
#pragma unroll
    for (int i = 0; i < 10; i++) {
        float v = maxr * ((float)(i + 1) * (1.0f / 11.0f));
        float t = (d - v) * invstep;
        float a = t + 1.0f, b = 1.0f - t;
        float e = 0.0f;
        if (a > 0.0f && b > 0.0f) e = EC * expf(-1.0f / a) * expf(-1.0f / b);
        emb[i] = e;
    }
}

// Per-path half-fc2 with f32x2 packed accumulation; weights from __constant__.
// hrow = this edge's 64 h values in SMEM (float4-vectorizable).
template <int U, int STRIDE>
__device__ __forceinline__ void fc2_half(const float* __restrict__ hrow, int off_half,
                                         float w[U * 4]) {
    uint64_t acc[U * 2];
#pragma unroll
    for (int o = 0; o < U * 2; o++) acc[o] = 0ull;
#pragma unroll
    for (int j4 = 0; j4 < 16; j4++) {
        float4 hv = *(const float4*)(hrow + j4 * 4);
        float hj[4] = {hv.x, hv.y, hv.z, hv.w};
#pragma unroll
        for (int t = 0; t < 4; t++) {
            int j = j4 * 4 + t;
            uint64_t h2 = pack2(hj[t], hj[t]);
            const ulonglong2* b2 = (const ulonglong2*)(c_w2 + j * STRIDE + off_half);
#pragma unroll
            for (int u = 0; u < U; u++) {
                ulonglong2 v = b2[u * 2];
                fma2(acc[u * 2 + 0], h2, v.x);
                fma2(acc[u * 2 + 1], h2, v.y);
            }
        }
    }
#pragma unroll
    for (int u = 0; u < U; u++) {
        float2 a = unpack2(acc[u * 2 + 0]);
        float2 b = unpack2(acc[u * 2 + 1]);
        w[u * 4 + 0] = a.x * 0.125f;
        w[u * 4 + 1] = a.y * 0.125f;
        w[u * 4 + 2] = b.x * 0.125f;
        w[u * 4 + 3] = b.y * 0.125f;
    }
}

// o[c][k] += pw * sum_{u,i,j} x1[u,i] sh[j] W3J[i,j,k] w[u,c]   (4 channels)
template <int L1, int L2, int L3>
__device__ __forceinline__ void tp_half(const float* __restrict__ x1,
                                        const float* __restrict__ sh,
                                        const float* __restrict__ w3,
                                        const float* __restrict__ w, float pw,
                                        float* __restrict__ o) {
    constexpr int I = 2 * L1 + 1, J = 2 * L2 + 1, K = 2 * L3 + 1;
    float C[I * K];
#pragma unroll
    for (int i = 0; i < I; i++)
#pragma unroll
        for (int k = 0; k < K; k++) {
            float a = 0.0f;
#pragma unroll
            for (int j = 0; j < J; j++) a += sh[j] * w3[(i * J + j) * K + k];
            C[i * K + k] = a;
        }
    float B[I * K];  // U == I
#pragma unroll
    for (int u = 0; u < I; u++)
#pragma unroll
        for (int k = 0; k < K; k++) {
            float a = 0.0f;
#pragma unroll
            for (int i = 0; i < I; i++) a += x1[u * I + i] * C[i * K + k];
            B[u * K + k] = a;
        }
#pragma unroll
    for (int c = 0; c < 4; c++)
#pragma unroll
        for (int k = 0; k < K; k++) {
            float a = 0.0f;
#pragma unroll
            for (int u = 0; u < I; u++) a += B[u * K + k] * w[u * 4 + c];
            o[c * K + k] += pw * a;
        }
}

// This half's 4 channels are contiguous 4K floats at ob + base + half*4*K,
// 16B-aligned (all bases are multiples of 4). Use vector reductions.
template <int K>
__device__ __forceinline__ void atomic_half(float* __restrict__ ob, int base, int half,
                                            float scale, const float* __restrict__ o) {
    float* p = ob + base + half * 4 * K;
#pragma unroll
    for (int q = 0; q < K; q++)
        red_add_v4(p + 4 * q, scale * o[4 * q + 0], scale * o[4 * q + 1],
                   scale * o[4 * q + 2], scale * o[4 * q + 3]);
}

// ---------------------------------------------------------------------------
// Node precompute: fsum slices -> g_nodefeat
// ---------------------------------------------------------------------------
__global__ void node_pre_kernel(const float* __restrict__ x, int n_nodes) {
    int idx = blockIdx.x * blockDim.x + threadIdx.x;
    if (idx >= n_nodes * NF_STRIDE) return;
    int n = idx / NF_STRIDE, t = idx % NF_STRIDE;
    if (t >= 35) { g_nodefeat[idx] = 0.0f; return; }
    int a, b;
    if (t == 0) { a = 0; b = 0; }
    else if (t < 10) { int u = (t - 1) / 3, i = (t - 1) % 3; a = 1 + u; b = 1 + i; }
    else { int u = (t - 10) / 5, i = (t - 10) % 5; a = 4 + u; b = 4 + i; }
    int base = n * 162 + (a * 9 + b) * 2;
    g_nodefeat[idx] = x[base] + x[base + 1];
}

// ---------------------------------------------------------------------------
// Edge kernel: 2 threads per edge (channel split), h in SMEM [edge][H_STRIDE],
// weights in __constant__. threads 0..127 -> half 0; 128..255 -> half 1.
// ---------------------------------------------------------------------------
template <int L1>
__global__ __launch_bounds__(256, 2) void edge_kernel(
    const int* __restrict__ ei, const float* __restrict__ pos, float* __restrict__ out,
    int E, const int* __restrict__ mrp, float scale, W3JParams W) {
    constexpr int STRIDE = (L1 == 0) ? 24 : (L1 == 1) ? 96 : 160;
    extern __shared__ float hsh[];   // 128 * H_STRIDE

    int eb = threadIdx.x & 127;
    int half = threadIdx.x >> 7;
    int e = blockIdx.x * 128 + eb;
    bool active = e < E;

    float sh1[3], sh2[5];
    int row = 0, col = 0;
    if (active) {
        float maxr = scalar_as_float(mrp);
        row = ei[e];
        col = ei[E + e];
        float emb[10];
        edge_common(row, col, pos, maxr, sh1, sh2, emb);
        // fc1 half: h[j] for j in [half*32, half*32+32), write via STS.128
        const float m = 0.44721359549995794f;  // sqrt(2)/sqrt(10)
        float* hr = hsh + eb * H_STRIDE + half * 32;
#pragma unroll
        for (int jj = 0; jj < 32; jj += 4) {
            float4 hv;
            float av[4];
#pragma unroll
            for (int t = 0; t < 4; t++) {
                int j = half * 32 + jj + t;
                float a = 0.0f;
#pragma unroll
                for (int k = 0; k < 10; k++) a += emb[k] * c_w1[k * 64 + j];
                av[t] = a > 0.0f ? a * m : 0.0f;
            }
            hv.x = av[0]; hv.y = av[1]; hv.z = av[2]; hv.w = av[3];
            *(float4*)(hr + jj) = hv;
        }
    }
    __syncthreads();
    if (!active) return;

    const float* hrow = hsh + eb * H_STRIDE;
    float* ob = out + (size_t)col * 216;
    const float one = 1.0f;
    int off_h = half * 4;

    if constexpr (L1 == 0) {
        float s0 = g_nodefeat[row * NF_STRIDE + 0];
        {
            float w[4], o[4] = {0};
            fc2_half<1, STRIDE>(hrow, 0 + off_h, w);
            tp_half<0, 0, 0>(&s0, &one, W.w000, w, 1.0f, o);
            atomic_half<1>(ob, 0, half, scale, o);
        }
        {
            float w[4], o[12] = {0};
            fc2_half<1, STRIDE>(hrow, 8 + off_h, w);
            tp_half<0, 1, 1>(&s0, sh1, W.w011, w, 1.7320508075688772f, o);
            atomic_half<3>(ob, 8, half, scale, o);
        }
        {
            float w[4], o[20] = {0};
            fc2_half<1, STRIDE>(hrow, 16 + off_h, w);
            tp_half<0, 2, 2>(&s0, sh2, W.w022, w, 2.23606797749979f, o);
            atomic_half<5>(ob, 32, half, scale, o);
        }
    } else if constexpr (L1 == 1) {
        float x1[9];
#pragma unroll
        for (int i = 0; i < 9; i++) x1[i] = g_nodefeat[row * NF_STRIDE + 1 + i];
        float o1[12] = {0};
        {
            float w[12];
            fc2_half<3, STRIDE>(hrow, 0 + off_h, w);
            tp_half<1, 0, 1>(x1, &one, W.w101, w, 0.7071067811865476f, o1);
        }
        {
            float w[12], o[4] = {0};
            fc2_half<3, STRIDE>(hrow, 24 + off_h, w);
            tp_half<1, 1, 0>(x1, sh1, W.w110, w, 0.5773502691896258f, o);
            atomic_half<1>(ob, 72, half, scale, o);
        }
        {
            float w[12], o[20] = {0};
            fc2_half<3, STRIDE>(hrow, 48 + off_h, w);
            tp_half<1, 1, 2>(x1, sh1, W.w112, w, 1.2909944487358056f, o);
            atomic_half<5>(ob, 104, half, scale, o);
        }
        {
            float w[12];
            fc2_half<3, STRIDE>(hrow, 72 + off_h, w);
            tp_half<1, 2, 1>(x1, sh2, W.w121, w, 0.7071067811865476f, o1);
        }
        atomic_half<3>(ob, 80, half, scale, o1);
    } else {
        float x1[25];
#pragma unroll
        for (int i = 0; i < 25; i++) x1[i] = g_nodefeat[row * NF_STRIDE + 10 + i];
        float o2[20] = {0};
        {
            float w[20];
            fc2_half<5, STRIDE>(hrow, 0 + off_h, w);
            tp_half<2, 0, 2>(x1, &one, W.w202, w, 0.7071067811865476f, o2);
        }
        {
            float w[20], o[12] = {0};
            fc2_half<5, STRIDE>(hrow, 40 + off_h, w);
            tp_half<2, 1, 1>(x1, sh1, W.w211, w, 0.7745966692414834f, o);
            atomic_half<3>(ob, 152, half, scale, o);
        }
        {
            float w[20], o[4] = {0};
            fc2_half<5, STRIDE>(hrow, 80 + off_h, w);
            tp_half<2, 2, 0>(x1, sh2, W.w220, w, 0.4472135954999579f, o);
            atomic_half<1>(ob, 144, half, scale, o);
        }
        {
            float w[20];
            fc2_half<5, STRIDE>(hrow, 120 + off_h, w);
            tp_half<2, 2, 2>(x1, sh2, W.w222, w, 0.7071067811865476f, o2);
        }
        atomic_half<5>(ob, 176, half, scale, o2);
    }
}

// ---------------------------------------------------------------------------
// Launch
// ---------------------------------------------------------------------------
extern "C" void kernel_launch(void* const* d_in, const int* in_sizes, int n_in, void* d_out,
                              int out_size) {
    const float* x = (const float*)d_in[0];
    const int* ei = (const int*)d_in[1];
    const float* pos = (const float*)d_in[2];
    const int* mrp = (const int*)d_in[3];
    const float* ws1 = (const float*)d_in[5];
    const float* ws2 = (const float*)d_in[6];
    const float* wp1 = (const float*)d_in[7];
    const float* wp2 = (const float*)d_in[8];
    const float* wd1 = (const float*)d_in[9];
    const float* wd2 = (const float*)d_in[10];

    int E = in_sizes[1] / 2;
    int n_nodes = out_size / 216;
    if (n_nodes > MAX_NODES) n_nodes = MAX_NODES;
    float scale = (float)std::sqrt((double)n_nodes / (double)E);

    W3JParams W;
    build_w3j(&W);

    size_t smem_edge = (size_t)(128 * H_STRIDE) * sizeof(float);
    cudaFuncSetAttribute(edge_kernel<0>, cudaFuncAttributeMaxDynamicSharedMemorySize,
                         (int)smem_edge);
    cudaFuncSetAttribute(edge_kernel<1>, cudaFuncAttributeMaxDynamicSharedMemorySize,
                         (int)smem_edge);
    cudaFuncSetAttribute(edge_kernel<2>, cudaFuncAttributeMaxDynamicSharedMemorySize,
                         (int)smem_edge);

    cudaMemsetAsync(d_out, 0, (size_t)out_size * sizeof(float));

    {
        int tot = n_nodes * NF_STRIDE;
        node_pre_kernel<<<(tot + 255) / 256, 256>>>(x, n_nodes);
    }
    int gb = (E + 127) / 128;

    // s-block
    cudaMemcpyToSymbolAsync(c_w1, ws1, 640 * sizeof(float), 0, cudaMemcpyDeviceToDevice);
    cudaMemcpyToSymbolAsync(c_w2, ws2, 64 * 24 * sizeof(float), 0, cudaMemcpyDeviceToDevice);
    edge_kernel<0><<<gb, 256, smem_edge>>>(ei, pos, (float*)d_out, E, mrp, scale, W);

    // p-block
    cudaMemcpyToSymbolAsync(c_w1, wp1, 640 * sizeof(float), 0, cudaMemcpyDeviceToDevice);
    cudaMemcpyToSymbolAsync(c_w2, wp2, 64 * 96 * sizeof(float), 0, cudaMemcpyDeviceToDevice);
    edge_kernel<1><<<gb, 256, smem_edge>>>(ei, pos, (float*)d_out, E, mrp, scale, W);

    // d-block
    cudaMemcpyToSymbolAsync(c_w1, wd1, 640 * sizeof(float), 0, cudaMemcpyDeviceToDevice);
    cudaMemcpyToSymbolAsync(c_w2, wd2, 64 * 160 * sizeof(float), 0, cudaMemcpyDeviceToDevice);
    edge_kernel<2><<<gb, 256, smem_edge>>>(ei, pos, (float*)d_out, E, mrp, scale, W);
}

// round 17
// speedup vs baseline: 4.7156x; 4.7156x over previous
#include <cuda_runtime.h>
#include <cstdint>
#include <cmath>
#include <complex>

// ---------------------------------------------------------------------------
// Problem constants
// ---------------------------------------------------------------------------
#define MAX_NODES 50000
#define NF_STRIDE 36   // 1 (s) + 9 (p) + 25 (d) + pad
#define H_STRIDE 68    // 64 + pad(4): conflict-free LDS.128/STS.128 layout

__device__ float g_nodefeat[MAX_NODES * NF_STRIDE];

// All real Wigner-3j tables, passed by value (constant bank, param space)
struct W3JParams {
    float w000[1];
    float w011[9];
    float w022[25];
    float w101[9];
    float w110[9];
    float w112[45];
    float w121[45];
    float w202[25];
    float w211[45];
    float w220[25];
    float w222[125];
};

// ---------------------------------------------------------------------------
// Host-side Wigner-3j computation (pure, cheap)
// ---------------------------------------------------------------------------
typedef std::complex<double> cd;

static double factd(int n) { double r = 1.0; for (int i = 2; i <= n; i++) r *= i; return r; }

static double cgc(int j1, int m1, int j2, int m2, int j3, int m3) {
    if (m1 + m2 != m3) return 0.0;
    double pre = std::sqrt((2.0 * j3 + 1.0) * factd(j1 + j2 - j3) * factd(j1 - j2 + j3) *
                           factd(-j1 + j2 + j3) / factd(j1 + j2 + j3 + 1));
    pre *= std::sqrt(factd(j1 + m1) * factd(j1 - m1) * factd(j2 + m2) * factd(j2 - m2) *
                     factd(j3 + m3) * factd(j3 - m3));
    int kmin = 0;
    if (j2 - j3 - m1 > kmin) kmin = j2 - j3 - m1;
    if (j1 - j3 + m2 > kmin) kmin = j1 - j3 + m2;
    int kmax = j1 + j2 - j3;
    if (j1 - m1 < kmax) kmax = j1 - m1;
    if (j2 + m2 < kmax) kmax = j2 + m2;
    double s = 0.0;
    for (int k = kmin; k <= kmax; k++) {
        double term = 1.0 / (factd(k) * factd(j1 + j2 - j3 - k) * factd(j1 - m1 - k) *
                             factd(j2 + m2 - k) * factd(j3 - j2 + m1 + k) * factd(j3 - j1 - m2 + k));
        s += (k & 1) ? -term : term;
    }
    return pre * s;
}

static void qmat(int l, cd* Q) {
    int n = 2 * l + 1;
    for (int i = 0; i < n * n; i++) Q[i] = cd(0, 0);
    Q[l * n + l] = cd(1, 0);
    double is2 = 1.0 / std::sqrt(2.0);
    for (int m = 1; m <= l; m++) {
        double sg = (m & 1) ? -1.0 : 1.0;
        Q[(l + m) * n + (l + m)] = cd(sg * is2, 0);
        Q[(l + m) * n + (l - m)] = cd(is2, 0);
        Q[(l - m) * n + (l - m)] = cd(0, is2);
        Q[(l - m) * n + (l + m)] = cd(0, -sg * is2);
    }
}

static void w3jfill(int l1, int l2, int l3, float* outv) {
    int n1 = 2 * l1 + 1, n2 = 2 * l2 + 1, n3 = 2 * l3 + 1;
    cd Q1[25], Q2[25], Q3[25];
    qmat(l1, Q1); qmat(l2, Q2); qmat(l3, Q3);
    cd R[125];
    for (int a = 0; a < n1; a++)
        for (int c = 0; c < n2; c++)
            for (int e = 0; e < n3; e++) {
                cd acc(0, 0);
                for (int b = 0; b < n1; b++)
                    for (int d = 0; d < n2; d++)
                        for (int f = 0; f < n3; f++) {
                            double Cv = cgc(l1, b - l1, l2, d - l2, l3, f - l3);
                            if (Cv == 0.0) continue;
                            acc += std::conj(Q1[a * n1 + b]) * std::conj(Q2[c * n2 + d]) *
                                   Q3[e * n3 + f] * Cv;
                        }
                R[(a * n2 + c) * n3 + e] = acc;
            }
    int N = n1 * n2 * n3;
    double mr = 0, mi = 0;
    for (int i = 0; i < N; i++) {
        double re = std::fabs(R[i].real()), im = std::fabs(R[i].imag());
        if (re > mr) mr = re;
        if (im > mi) mi = im;
    }
    double tmp[125];
    if (mi > mr)
        for (int i = 0; i < N; i++) tmp[i] = R[i].imag();
    else
        for (int i = 0; i < N; i++) tmp[i] = R[i].real();
    double nrm = 0;
    for (int i = 0; i < N; i++) nrm += tmp[i] * tmp[i];
    nrm = std::sqrt(nrm);
    for (int i = 0; i < N; i++) outv[i] = (float)(tmp[i] / nrm);
}

static void build_w3j(W3JParams* W) {
    w3jfill(0, 0, 0, W->w000);
    w3jfill(0, 1, 1, W->w011);
    w3jfill(0, 2, 2, W->w022);
    w3jfill(1, 0, 1, W->w101);
    w3jfill(1, 1, 0, W->w110);
    w3jfill(1, 1, 2, W->w112);
    w3jfill(1, 2, 1, W->w121);
    w3jfill(2, 0, 2, W->w202);
    w3jfill(2, 1, 1, W->w211);
    w3jfill(2, 2, 0, W->w220);
    w3jfill(2, 2, 2, W->w222);
}

// ---------------------------------------------------------------------------
// f32x2 packed-FMA helpers (sm_103a; PTX-only instruction)
// ---------------------------------------------------------------------------
__device__ __forceinline__ uint64_t pack2(float lo, float hi) {
    uint64_t r;
    asm("mov.b64 %0, {%1, %2};" : "=l"(r) : "f"(lo), "f"(hi));
    return r;
}
__device__ __forceinline__ void fma2(uint64_t& d, uint64_t a, uint64_t b) {
    asm("fma.rn.f32x2 %0, %1, %2, %0;" : "+l"(d) : "l"(a), "l"(b));
}
__device__ __forceinline__ float2 unpack2(uint64_t v) {
    float2 f;
    asm("mov.b64 {%0, %1}, %2;" : "=f"(f.x), "=f"(f.y) : "l"(v));
    return f;
}

// Vector reduction: 4 contiguous f32 atomic adds in one L1TEX wavefront.
__device__ __forceinline__ void red_add_v4(float* p, float a, float b, float c, float d) {
    asm volatile("red.global.add.v4.f32 [%0], {%1, %2, %3, %4};"
                 :: "l"(p), "f"(a), "f"(b), "f"(c), "f"(d)
                 : "memory");
}

// ---------------------------------------------------------------------------
// Device helpers
// ---------------------------------------------------------------------------
__device__ __forceinline__ float scalar_as_float(const int* p) {
    int iv = *p;
    return (iv > -100000000 && iv < 100000000) ? (float)iv : __int_as_float(iv);
}

__device__ __forceinline__ void edge_common(int row, int col, const float* __restrict__ pos,
                                            float maxr, float sh1[3], float sh2[5],
                                            float emb[10]) {
    float vx = pos[3 * row + 0] - pos[3 * col + 0];
    float vy = pos[3 * row + 1] - pos[3 * col + 1];
    float vz = pos[3 * row + 2] - pos[3 * col + 2];
    float d = sqrtf(vx * vx + vy * vy + vz * vz + 1e-12f);
    float inv = 1.0f / d;
    float x = vx * inv, y = vy * inv, z = vz * inv;
    sh1[0] = 1.7320508075688772f * y;
    sh1[1] = 1.7320508075688772f * z;
    sh1[2] = 1.7320508075688772f * x;
    sh2[0] = 3.872983346207417f * x * y;
    sh2[1] = 3.872983346207417f * y * z;
    sh2[2] = 1.118033988749895f * (3.0f * z * z - 1.0f);
    sh2[3] = 3.872983346207417f * x * z;
    sh2[4] = 1.9364916731037085f * (x * x - y * y);

    float invstep = 11.0f / maxr;
    const float EC = 26.6692982f;  // 1.14136 * e^2 * sqrt(10)
#pragma unroll
    for (int i = 0; i < 10; i++) {
        float v = maxr * ((float)(i + 1) * (1.0f / 11.0f));
        float t = (d - v) * invstep;
        float a = t + 1.0f, b = 1.0f - t;
        float e = 0.0f;
        if (a > 0.0f && b > 0.0f) e = EC * expf(-1.0f / a) * expf(-1.0f / b);
        emb[i] = e;
    }
}

// Per-path half-fc2 with f32x2 packed accumulation.
// hrow = this edge's 64 h values in SMEM (float4-vectorizable).
// sw2 broadcast LDS.128 as ulonglong2.
template <int U, int STRIDE>
__device__ __forceinline__ void fc2_half(const float* __restrict__ hrow,
                                         const float* __restrict__ sw2, int off_half,
                                         float w[U * 4]) {
    uint64_t acc[U * 2];
#pragma unroll
    for (int o = 0; o < U * 2; o++) acc[o] = 0ull;
#pragma unroll
    for (int j4 = 0; j4 < 16; j4++) {
        float4 hv = *(const float4*)(hrow + j4 * 4);
        float hj[4] = {hv.x, hv.y, hv.z, hv.w};
#pragma unroll
        for (int t = 0; t < 4; t++) {
            int j = j4 * 4 + t;
            uint64_t h2 = pack2(hj[t], hj[t]);
            const ulonglong2* b2 = (const ulonglong2*)(sw2 + j * STRIDE + off_half);
#pragma unroll
            for (int u = 0; u < U; u++) {
                ulonglong2 v = b2[u * 2];
                fma2(acc[u * 2 + 0], h2, v.x);
                fma2(acc[u * 2 + 1], h2, v.y);
            }
        }
    }
#pragma unroll
    for (int u = 0; u < U; u++) {
        float2 a = unpack2(acc[u * 2 + 0]);
        float2 b = unpack2(acc[u * 2 + 1]);
        w[u * 4 + 0] = a.x * 0.125f;
        w[u * 4 + 1] = a.y * 0.125f;
        w[u * 4 + 2] = b.x * 0.125f;
        w[u * 4 + 3] = b.y * 0.125f;
    }
}

// o[c][k] += pw * sum_{u,i,j} x1[u,i] sh[j] W3J[i,j,k] w[u,c]   (4 channels)
template <int L1, int L2, int L3>
__device__ __forceinline__ void tp_half(const float* __restrict__ x1,
                                        const float* __restrict__ sh,
                                        const float* __restrict__ w3,
                                        const float* __restrict__ w, float pw,
                                        float* __restrict__ o) {
    constexpr int I = 2 * L1 + 1, J = 2 * L2 + 1, K = 2 * L3 + 1;
    float C[I * K];
#pragma unroll
    for (int i = 0; i < I; i++)
#pragma unroll
        for (int k = 0; k < K; k++) {
            float a = 0.0f;
#pragma unroll
            for (int j = 0; j < J; j++) a += sh[j] * w3[(i * J + j) * K + k];
            C[i * K + k] = a;
        }
    float B[I * K];  // U == I
#pragma unroll
    for (int u = 0; u < I; u++)
#pragma unroll
        for (int k = 0; k < K; k++) {
            float a = 0.0f;
#pragma unroll
            for (int i = 0; i < I; i++) a += x1[u * I + i] * C[i * K + k];
            B[u * K + k] = a;
        }
#pragma unroll
    for (int c = 0; c < 4; c++)
#pragma unroll
        for (int k = 0; k < K; k++) {
            float a = 0.0f;
#pragma unroll
            for (int u = 0; u < I; u++) a += B[u * K + k] * w[u * 4 + c];
            o[c * K + k] += pw * a;
        }
}

// This half's 4 channels are contiguous 4K floats at ob + base + half*4*K,
// 16B-aligned (all bases are multiples of 4). Use vector reductions.
template <int K>
__device__ __forceinline__ void atomic_half(float* __restrict__ ob, int base, int half,
                                            float scale, const float* __restrict__ o) {
    float* p = ob + base + half * 4 * K;
#pragma unroll
    for (int q = 0; q < K; q++)
        red_add_v4(p + 4 * q, scale * o[4 * q + 0], scale * o[4 * q + 1],
                   scale * o[4 * q + 2], scale * o[4 * q + 3]);
}

// ---------------------------------------------------------------------------
// Node precompute: fsum slices -> g_nodefeat
// ---------------------------------------------------------------------------
__global__ void node_pre_kernel(const float* __restrict__ x, int n_nodes) {
    int idx = blockIdx.x * blockDim.x + threadIdx.x;
    if (idx >= n_nodes * NF_STRIDE) return;
    int n = idx / NF_STRIDE, t = idx % NF_STRIDE;
    if (t >= 35) { g_nodefeat[idx] = 0.0f; return; }
    int a, b;
    if (t == 0) { a = 0; b = 0; }
    else if (t < 10) { int u = (t - 1) / 3, i = (t - 1) % 3; a = 1 + u; b = 1 + i; }
    else { int u = (t - 10) / 5, i = (t - 10) % 5; a = 4 + u; b = 4 + i; }
    int base = n * 162 + (a * 9 + b) * 2;
    g_nodefeat[idx] = x[base] + x[base + 1];
}

// ---------------------------------------------------------------------------
// Edge kernel: 2 threads per edge (channel split), h in SMEM [edge][H_STRIDE],
// w1/w2 in SMEM. threads 0..127 -> half 0; 128..255 -> half 1.
// ---------------------------------------------------------------------------
template <int L1>
__global__ __launch_bounds__(256, 2) void edge_kernel(
    const int* __restrict__ ei, const float* __restrict__ pos,
    const float* __restrict__ w1g, const float* __restrict__ w2g, float* __restrict__ out,
    int E, const int* __restrict__ mrp, float scale, W3JParams W) {
    constexpr int STRIDE = (L1 == 0) ? 24 : (L1 == 1) ? 96 : 160;
    extern __shared__ float dsm[];
    float* sw1 = dsm;                     // 640
    float* sw2 = dsm + 640;               // 64*STRIDE
    float* hsh = sw2 + 64 * STRIDE;       // 128*H_STRIDE

    for (int i = threadIdx.x; i < 640; i += 256) sw1[i] = w1g[i];
    for (int i = threadIdx.x; i < 64 * STRIDE; i += 256) sw2[i] = w2g[i];
    __syncthreads();

    int eb = threadIdx.x & 127;
    int half = threadIdx.x >> 7;
    int e = blockIdx.x * 128 + eb;
    bool active = e < E;

    float sh1[3], sh2[5];
    int row = 0, col = 0;
    if (active) {
        float maxr = scalar_as_float(mrp);
        row = ei[e];
        col = ei[E + e];
        float emb[10];
        edge_common(row, col, pos, maxr, sh1, sh2, emb);
        // fc1 half: h[j] for j in [half*32, half*32+32), write via STS.128
        const float m = 0.44721359549995794f;  // sqrt(2)/sqrt(10)
        float* hr = hsh + eb * H_STRIDE + half * 32;
#pragma unroll
        for (int jj = 0; jj < 32; jj += 4) {
            float4 hv;
            float av[4];
#pragma unroll
            for (int t = 0; t < 4; t++) {
                int j = half * 32 + jj + t;
                float a = 0.0f;
#pragma unroll
                for (int k = 0; k < 10; k++) a += emb[k] * sw1[k * 64 + j];
                av[t] = a > 0.0f ? a * m : 0.0f;
            }
            hv.x = av[0]; hv.y = av[1]; hv.z = av[2]; hv.w = av[3];
            *(float4*)(hr + jj) = hv;
        }
    }
    __syncthreads();
    if (!active) return;

    const float* hrow = hsh + eb * H_STRIDE;
    float* ob = out + (size_t)col * 216;
    const float one = 1.0f;
    int off_h = half * 4;

    if constexpr (L1 == 0) {
        float s0 = g_nodefeat[row * NF_STRIDE + 0];
        {
            float w[4], o[4] = {0};
            fc2_half<1, STRIDE>(hrow, sw2, 0 + off_h, w);
            tp_half<0, 0, 0>(&s0, &one, W.w000, w, 1.0f, o);
            atomic_half<1>(ob, 0, half, scale, o);
        }
        {
            float w[4], o[12] = {0};
            fc2_half<1, STRIDE>(hrow, sw2, 8 + off_h, w);
            tp_half<0, 1, 1>(&s0, sh1, W.w011, w, 1.7320508075688772f, o);
            atomic_half<3>(ob, 8, half, scale, o);
        }
        {
            float w[4], o[20] = {0};
            fc2_half<1, STRIDE>(hrow, sw2, 16 + off_h, w);
            tp_half<0, 2, 2>(&s0, sh2, W.w022, w, 2.23606797749979f, o);
            atomic_half<5>(ob, 32, half, scale, o);
        }
    } else if constexpr (L1 == 1) {
        float x1[9];
#pragma unroll
        for (int i = 0; i < 9; i++) x1[i] = g_nodefeat[row * NF_STRIDE + 1 + i];
        float o1[12] = {0};
        {
            float w[12];
            fc2_half<3, STRIDE>(hrow, sw2, 0 + off_h, w);
            tp_half<1, 0, 1>(x1, &one, W.w101, w, 0.7071067811865476f, o1);
        }
        {
            float w[12], o[4] = {0};
            fc2_half<3, STRIDE>(hrow, sw2, 24 + off_h, w);
            tp_half<1, 1, 0>(x1, sh1, W.w110, w, 0.5773502691896258f, o);
            atomic_half<1>(ob, 72, half, scale, o);
        }
        {
            float w[12], o[20] = {0};
            fc2_half<3, STRIDE>(hrow, sw2, 48 + off_h, w);
            tp_half<1, 1, 2>(x1, sh1, W.w112, w, 1.2909944487358056f, o);
            atomic_half<5>(ob, 104, half, scale, o);
        }
        {
            float w[12];
            fc2_half<3, STRIDE>(hrow, sw2, 72 + off_h, w);
            tp_half<1, 2, 1>(x1, sh2, W.w121, w, 0.7071067811865476f, o1);
        }
        atomic_half<3>(ob, 80, half, scale, o1);
    } else {
        float x1[25];
#pragma unroll
        for (int i = 0; i < 25; i++) x1[i] = g_nodefeat[row * NF_STRIDE + 10 + i];
        float o2[20] = {0};
        {
            float w[20];
            fc2_half<5, STRIDE>(hrow, sw2, 0 + off_h, w);
            tp_half<2, 0, 2>(x1, &one, W.w202, w, 0.7071067811865476f, o2);
        }
        {
            float w[20], o[12] = {0};
            fc2_half<5, STRIDE>(hrow, sw2, 40 + off_h, w);
            tp_half<2, 1, 1>(x1, sh1, W.w211, w, 0.7745966692414834f, o);
            atomic_half<3>(ob, 152, half, scale, o);
        }
        {
            float w[20], o[4] = {0};
            fc2_half<5, STRIDE>(hrow, sw2, 80 + off_h, w);
            tp_half<2, 2, 0>(x1, sh2, W.w220, w, 0.4472135954999579f, o);
            atomic_half<1>(ob, 144, half, scale, o);
        }
        {
            float w[20];
            fc2_half<5, STRIDE>(hrow, sw2, 120 + off_h, w);
            tp_half<2, 2, 2>(x1, sh2, W.w222, w, 0.7071067811865476f, o2);
        }
        atomic_half<5>(ob, 176, half, scale, o2);
    }
}

// ---------------------------------------------------------------------------
// Launch
// ---------------------------------------------------------------------------
extern "C" void kernel_launch(void* const* d_in, const int* in_sizes, int n_in, void* d_out,
                              int out_size) {
    const float* x = (const float*)d_in[0];
    const int* ei = (const int*)d_in[1];
    const float* pos = (const float*)d_in[2];
    const int* mrp = (const int*)d_in[3];
    const float* ws1 = (const float*)d_in[5];
    const float* ws2 = (const float*)d_in[6];
    const float* wp1 = (const float*)d_in[7];
    const float* wp2 = (const float*)d_in[8];
    const float* wd1 = (const float*)d_in[9];
    const float* wd2 = (const float*)d_in[10];

    int E = in_sizes[1] / 2;
    int n_nodes = out_size / 216;
    if (n_nodes > MAX_NODES) n_nodes = MAX_NODES;
    float scale = (float)std::sqrt((double)n_nodes / (double)E);

    W3JParams W;
    build_w3j(&W);

    size_t smem_s = (640 + 64 * 24 + 128 * H_STRIDE) * sizeof(float);
    size_t smem_p = (640 + 64 * 96 + 128 * H_STRIDE) * sizeof(float);
    size_t smem_d = (640 + 64 * 160 + 128 * H_STRIDE) * sizeof(float);
    cudaFuncSetAttribute(edge_kernel<0>, cudaFuncAttributeMaxDynamicSharedMemorySize,
                         (int)smem_s);
    cudaFuncSetAttribute(edge_kernel<1>, cudaFuncAttributeMaxDynamicSharedMemorySize,
                         (int)smem_p);
    cudaFuncSetAttribute(edge_kernel<2>, cudaFuncAttributeMaxDynamicSharedMemorySize,
                         (int)smem_d);

    cudaMemsetAsync(d_out, 0, (size_t)out_size * sizeof(float));

    {
        int tot = n_nodes * NF_STRIDE;
        node_pre_kernel<<<(tot + 255) / 256, 256>>>(x, n_nodes);
    }
    int gb = (E + 127) / 128;
    edge_kernel<0><<<gb, 256, smem_s>>>(ei, pos, ws1, ws2, (float*)d_out, E, mrp, scale, W);
    edge_kernel<1><<<gb, 256, smem_p>>>(ei, pos, wp1, wp2, (float*)d_out, E, mrp, scale, W);
    edge_kernel<2><<<gb, 256, smem_d>>>(ei, pos, wd1, wd2, (float*)d_out, E, mrp, scale, W);
}